// round 10
// baseline (speedup 1.0000x reference)
#include <cuda_runtime.h>
#include <cuda_bf16.h>
#include <math.h>
#include <stdint.h>

#define BB 64
#define TT 512
#define NKEY 512
#define DD 256

// Scratch (device globals: allocation-free per harness rules)
__device__ __nv_bfloat16 g_xb[BB*TT*DD];
__device__ __nv_bfloat16 g_hb[BB*NKEY*DD];
__device__ __nv_bfloat16 g_kb[BB*NKEY*DD];
__device__ __nv_bfloat16 g_vb[BB*NKEY*DD];
__device__ __nv_bfloat16 g_wTb[3*DD*DD];   // transposed weights [z][n][k], bf16
__device__ float g_pmax[BB*4*DD];

// ---------------------------------------------------------------------------
// helpers (base PTX ISA, valid on sm_100 target)
// ---------------------------------------------------------------------------
__device__ __forceinline__ uint32_t smem_u32(const void* p) {
    uint32_t a;
    asm("{ .reg .u64 t; cvta.to.shared.u64 t, %1; cvt.u32.u64 %0, t; }" : "=r"(a) : "l"(p));
    return a;
}
__device__ __forceinline__ void mma_bf16(float* d, const uint32_t* a, uint32_t b0, uint32_t b1) {
    asm volatile(
        "mma.sync.aligned.m16n8k16.row.col.f32.bf16.bf16.f32 "
        "{%0,%1,%2,%3}, {%4,%5,%6,%7}, {%8,%9}, {%0,%1,%2,%3};"
        : "+f"(d[0]), "+f"(d[1]), "+f"(d[2]), "+f"(d[3])
        : "r"(a[0]), "r"(a[1]), "r"(a[2]), "r"(a[3]), "r"(b0), "r"(b1));
}
__device__ __forceinline__ void ldm_x4(uint32_t* r, uint32_t addr) {
    asm volatile("ldmatrix.sync.aligned.m8n8.x4.shared.b16 {%0,%1,%2,%3}, [%4];"
        : "=r"(r[0]), "=r"(r[1]), "=r"(r[2]), "=r"(r[3]) : "r"(addr));
}
__device__ __forceinline__ void ldm_x4_t(uint32_t* r, uint32_t addr) {
    asm volatile("ldmatrix.sync.aligned.m8n8.x4.trans.shared.b16 {%0,%1,%2,%3}, [%4];"
        : "=r"(r[0]), "=r"(r[1]), "=r"(r[2]), "=r"(r[3]) : "r"(addr));
}
__device__ __forceinline__ void cp_async16(uint32_t dst, const void* src) {
    asm volatile("cp.async.cg.shared.global [%0], [%1], 16;" :: "r"(dst), "l"(src));
}
#define CP_COMMIT() asm volatile("cp.async.commit_group;" ::: "memory")
#define CP_WAIT(n)  asm volatile("cp.async.wait_group %0;" :: "n"(n) : "memory")

// ---------------------------------------------------------------------------
// K_pre: fused (a) h->bf16 convert, (b) build x, (c) weight transpose.
// ---------------------------------------------------------------------------
#define PRE_PREP 8192
#define PRE_BX   (PRE_PREP + 4096)
#define PRE_END  (PRE_BX + 24)

__global__ __launch_bounds__(256) void k_pre(const float* __restrict__ h,
        const float* __restrict__ traj, const int* __restrict__ labels,
        const float* __restrict__ emb, const float* __restrict__ w_mlp,
        const float* __restrict__ b_mlp, const float* __restrict__ ln_g,
        const float* __restrict__ ln_b, const float* __restrict__ wq,
        const float* __restrict__ wk, const float* __restrict__ wv) {
    __shared__ float s[32*257];
    int bx = blockIdx.x;
    int tid = threadIdx.x;

    if (bx < PRE_PREP) {
        size_t i = (size_t)bx * 256 + tid;
        float4 v = *(const float4*)&h[i*4];
        __nv_bfloat162 p0 = __floats2bfloat162_rn(v.x, v.y);
        __nv_bfloat162 p1 = __floats2bfloat162_rn(v.z, v.w);
        uint32_t* dst = (uint32_t*)&g_hb[i*4];
        dst[0] = *(uint32_t*)&p0;
        dst[1] = *(uint32_t*)&p1;
    } else if (bx < PRE_BX) {
        int warp = tid >> 5, lane = tid & 31;
        int row = (bx - PRE_PREP)*8 + warp;
        int b = row >> 9;
        float t0 = traj[row*2 + 0];
        float t1 = traj[row*2 + 1];
        int lab = labels[b];
        float v[8];
        float sm = 0.f, s2 = 0.f;
        #pragma unroll
        for (int j = 0; j < 8; j++) {
            int d = lane + 32*j;
            v[j] = t0*w_mlp[d] + t1*w_mlp[DD + d] + b_mlp[d];
            sm += v[j]; s2 += v[j]*v[j];
        }
        #pragma unroll
        for (int o = 16; o; o >>= 1) {
            sm += __shfl_xor_sync(0xFFFFFFFFu, sm, o);
            s2 += __shfl_xor_sync(0xFFFFFFFFu, s2, o);
        }
        float mu  = sm * (1.f/DD);
        float var = s2 * (1.f/DD) - mu*mu;
        float rs  = rsqrtf(var + 1e-5f);
        __nv_bfloat16* dst = g_xb + (size_t)row*DD;
        #pragma unroll
        for (int j = 0; j < 8; j++) {
            int d = lane + 32*j;
            float y = (v[j] - mu) * rs * ln_g[d] + ln_b[d];
            y = (y >= 0.f) ? y : 0.01f * y;
            y += emb[lab*DD + d];
            dst[d] = __float2bfloat16(y);
        }
    } else {
        int idx = bx - PRE_BX;
        int z = idx >> 3;
        int k0 = (idx & 7) * 32;
        const float* W = (z == 0) ? wq : (z == 1) ? wk : wv;
        #pragma unroll
        for (int i = 0; i < 32; i++) {
            int f = tid + i*256;
            int k = f >> 8, n = f & 255;
            s[k*257 + n] = W[(k0 + k)*DD + n];
        }
        __syncthreads();
        int n = tid;
        __nv_bfloat16* dst = &g_wTb[(size_t)z*DD*DD + (size_t)n*DD + k0];
        #pragma unroll
        for (int j = 0; j < 32; j++)
            dst[j] = __float2bfloat16(s[j*257 + n]);
    }
}

// ---------------------------------------------------------------------------
// K2: bf16 mma GEMM for K and V only (Q fused into attention).
// blockIdx.y: 0,1 -> k n-tiles; 2,3 -> v. valid_len tile-skip on all tiles.
// ---------------------------------------------------------------------------
#define GS 36
#define QKV_BUF (2*128*GS)
#define QKV_SMEM (2*QKV_BUF*4)

__global__ __launch_bounds__(256) void k_qkv_tc(const float* __restrict__ bk,
        const float* __restrict__ bv, const int* __restrict__ valid_len) {
    {
        int bb = blockIdx.x >> 2;
        int tib = blockIdx.x & 3;
        if (tib * 128 >= valid_len[bb]) return;
    }

    extern __shared__ uint32_t qsm[];
    uint32_t base = smem_u32(qsm);

    int tid = threadIdx.x;
    int wid = tid >> 5, lane = tid & 31;
    int g = lane >> 2, t = lane & 3;
    int wm = wid & 3, wn = wid >> 2;
    int l7 = lane & 7, lh = (lane >> 3) & 1, lq = lane >> 4;
    int y = blockIdx.y;
    int z = (y >> 1) + 1;                  // 1 = k, 2 = v
    int m0 = blockIdx.x * 128;
    int n0 = (y & 1) * 128;

    const __nv_bfloat16* A  = g_hb;
    const __nv_bfloat16* WT = g_wTb + (size_t)z*DD*DD;
    const float* bias = (z == 1) ? bk : bv;
    __nv_bfloat16* Out = (z == 1) ? g_kb : g_vb;

    auto fill = [&](int buf, int kc) {
        uint32_t ab = base + (uint32_t)buf*QKV_BUF*4;
        uint32_t bb = ab + 128*GS*4;
        int k0 = kc * 64;
        #pragma unroll
        for (int i = 0; i < 4; i++) {
            int f = tid + i*256;
            int r = f >> 3, cu = (f & 7) * 4;
            cp_async16(ab + (uint32_t)(r*GS + cu)*4, A  + (size_t)(m0 + r)*DD + k0 + cu*2);
            cp_async16(bb + (uint32_t)(r*GS + cu)*4, WT + (size_t)(n0 + r)*DD + k0 + cu*2);
        }
    };

    float acc[2][8][4];
    #pragma unroll
    for (int mf = 0; mf < 2; mf++)
        #pragma unroll
        for (int nf = 0; nf < 8; nf++)
            #pragma unroll
            for (int i = 0; i < 4; i++) acc[mf][nf][i] = 0.f;

    fill(0, 0);
    CP_COMMIT();

    for (int kc = 0; kc < 4; kc++) {
        int buf = kc & 1;
        if (kc < 3) { fill(buf ^ 1, kc + 1); CP_COMMIT(); CP_WAIT(1); }
        else        { CP_WAIT(0); }
        __syncthreads();

        uint32_t asb = base + (uint32_t)buf*QKV_BUF*4;
        uint32_t bsb = asb + 128*GS*4;
        #pragma unroll
        for (int s = 0; s < 4; s++) {
            uint32_t a[2][4];
            #pragma unroll
            for (int mf = 0; mf < 2; mf++) {
                int row = wm*32 + mf*16 + l7 + lh*8;
                ldm_x4(a[mf], asb + (uint32_t)(row*GS + s*8 + lq*4)*4);
            }
            #pragma unroll
            for (int np = 0; np < 4; np++) {
                uint32_t b[4];
                int row = wn*64 + np*16 + lq*8 + l7;
                ldm_x4(b, bsb + (uint32_t)(row*GS + s*8 + lh*4)*4);
                mma_bf16(acc[0][np*2],   a[0], b[0], b[1]);
                mma_bf16(acc[1][np*2],   a[1], b[0], b[1]);
                mma_bf16(acc[0][np*2+1], a[0], b[2], b[3]);
                mma_bf16(acc[1][np*2+1], a[1], b[2], b[3]);
            }
        }
        __syncthreads();
    }

    #pragma unroll
    for (int mf = 0; mf < 2; mf++) {
        int r = m0 + wm*32 + mf*16 + g;
        #pragma unroll
        for (int nf = 0; nf < 8; nf++) {
            int col = n0 + wn*64 + nf*8 + 2*t;
            float b0 = bias[col], b1 = bias[col+1];
            __nv_bfloat162 v0 = __floats2bfloat162_rn(acc[mf][nf][0]+b0, acc[mf][nf][1]+b1);
            __nv_bfloat162 v1 = __floats2bfloat162_rn(acc[mf][nf][2]+b0, acc[mf][nf][3]+b1);
            *(uint32_t*)&Out[(size_t)r*DD + col]     = *(uint32_t*)&v0;
            *(uint32_t*)&Out[(size_t)(r+8)*DD + col] = *(uint32_t*)&v1;
        }
    }
}

// ---------------------------------------------------------------------------
// K3: bf16 mma flash attention, 128-row t-tiles, FUSED Q projection,
// fused max pool. Grid (4, 64), 512 threads / 16 warps.
// Phase A: Q = (x @ wq + bq)/16 in-CTA. x tile lives in K0+K1 region
// (128 rows x 132 u32 = exactly both buffers); wq^T streamed in 4 chunks of
// 64 n-rows, double-buffered through V_U / SS_U regions.
// Commit groups: G0={x,c0} G1={c1} G2={c2,@ch0} G3={c3,@ch1}.
// Wait ladder: pre-loop WAIT(1)->G0; ch0 WAIT(1)->G1; ch1 WAIT(1)->G2;
// ch2 WAIT(0)->G3 (WAIT(1) would be a no-op race).
// ---------------------------------------------------------------------------
#define TSU 132
#define QS_U 0
#define K0_U 16896
#define K1_U 25344
#define V_U  33792
#define SS_U 42240
#define MR_U 50944
#define LR_U 51072
#define CR_U 51200
#define ATTN_SMEM (51328*4)    // 205312 B

__device__ __forceinline__ void tile_cp64(uint32_t dst_base, const __nv_bfloat16* src, int tid) {
    #pragma unroll
    for (int i = 0; i < 4; i++) {
        int c = tid + i*512;
        int r = c >> 5, o = c & 31;
        cp_async16(dst_base + (uint32_t)(r*TSU + o*4)*4, src + (size_t)r*DD + o*8);
    }
}
__device__ __forceinline__ void tile_cp128(uint32_t dst_base, const __nv_bfloat16* src, int tid) {
    #pragma unroll
    for (int i = 0; i < 8; i++) {
        int c = tid + i*512;
        int r = c >> 5, o = c & 31;
        cp_async16(dst_base + (uint32_t)(r*TSU + o*4)*4, src + (size_t)r*DD + o*8);
    }
}

__global__ __launch_bounds__(512, 1) void k_attn_tc(const int* __restrict__ valid_len,
                                                    const float* __restrict__ bq) {
    extern __shared__ uint32_t smu[];
    uint32_t base = smem_u32(smu);
    float* Ssf  = (float*)(smu + SS_U);
    float* mrow = (float*)(smu + MR_U);
    float* lrow = (float*)(smu + LR_U);
    float* crow = (float*)(smu + CR_U);

    int tid = threadIdx.x;
    int wid = tid >> 5, lane = tid & 31;
    int g = lane >> 2, t = lane & 3;
    int l7 = lane & 7, lh = (lane >> 3) & 1, lq = lane >> 4;
    int wm = wid >> 1, wn = wid & 1;
    int b = blockIdx.y, ttile = blockIdx.x;
    int vlen = valid_len[b];
    int ntiles = (vlen + 63) >> 6;
    int r0 = wm*16 + g;

    const __nv_bfloat16* xg  = g_xb + (size_t)(b*TT + ttile*128)*DD;
    const __nv_bfloat16* wqT = g_wTb;                     // z = 0
    const __nv_bfloat16* kg  = g_kb + (size_t)b*NKEY*DD;
    const __nv_bfloat16* vg  = g_vb + (size_t)b*NKEY*DD;

    // ---- Phase A: Q = (x @ wq + bq) * 1/16 -> Qs (bf16) ----
    tile_cp128(base + K0_U*4, xg, tid);                   // x (fills K0+K1)
    tile_cp64(base + V_U*4, wqT, tid);                    // wq chunk 0
    CP_COMMIT();                                          // G0
    tile_cp64(base + SS_U*4, wqT + (size_t)64*DD, tid);   // wq chunk 1
    CP_COMMIT();                                          // G1
    if (tid < 128) { mrow[tid] = -INFINITY; lrow[tid] = 0.f; }

    CP_WAIT(1);                                           // G0 done: x + chunk0
    __syncthreads();
    #pragma unroll
    for (int ch = 0; ch < 4; ch++) {
        uint32_t WB = base + ((ch & 1) ? SS_U : V_U)*4;
        float sacc[4][4];
        #pragma unroll
        for (int nf = 0; nf < 4; nf++)
            #pragma unroll
            for (int i = 0; i < 4; i++) sacc[nf][i] = 0.f;
        #pragma unroll 4
        for (int s = 0; s < 16; s++) {
            uint32_t a[4];
            int arow = wm*16 + l7 + lh*8;
            ldm_x4(a, base + (uint32_t)(K0_U + arow*TSU + s*8 + lq*4)*4);
            #pragma unroll
            for (int np = 0; np < 2; np++) {
                uint32_t bfr[4];
                int brow = wn*32 + np*16 + lq*8 + l7;
                ldm_x4(bfr, WB + (uint32_t)(brow*TSU + s*8 + lh*4)*4);
                mma_bf16(sacc[np*2],   a, bfr[0], bfr[1]);
                mma_bf16(sacc[np*2+1], a, bfr[2], bfr[3]);
            }
        }
        // epilogue: (acc + bq) * 1/16 -> bf16 into Qs
        #pragma unroll
        for (int nf = 0; nf < 4; nf++) {
            int col = ch*64 + wn*32 + nf*8 + 2*t;
            float b0 = bq[col], b1 = bq[col+1];
            __nv_bfloat162 v0 = __floats2bfloat162_rn((sacc[nf][0]+b0)*0.0625f,
                                                      (sacc[nf][1]+b1)*0.0625f);
            __nv_bfloat162 v1 = __floats2bfloat162_rn((sacc[nf][2]+b0)*0.0625f,
                                                      (sacc[nf][3]+b1)*0.0625f);
            smu[QS_U + r0*TSU + (col >> 1)]     = *(uint32_t*)&v0;
            smu[QS_U + (r0+8)*TSU + (col >> 1)] = *(uint32_t*)&v1;
        }
        __syncthreads();                                  // all reads of WB done
        if (ch < 2) {
            tile_cp64(WB, wqT + (size_t)(ch + 2)*64*DD, tid);  // chunk ch+2
            CP_COMMIT();                                  // G2 / G3
        }
        if (ch == 0 || ch == 1) { CP_WAIT(1); __syncthreads(); }
        else if (ch == 2)       { CP_WAIT(0); __syncthreads(); }
    }
    // x region (K0+K1) now dead; stream in K tile 0
    __syncthreads();
    tile_cp64(base + K0_U*4, kg, tid);
    CP_COMMIT();

    float accO[16][4];
    #pragma unroll
    for (int nf = 0; nf < 16; nf++)
        #pragma unroll
        for (int i = 0; i < 4; i++) accO[nf][i] = 0.f;

    // ---- Phase B: flash attention main loop (proven R7/R8 structure) ----
    for (int nt = 0; nt < ntiles; nt++) {
        int n0 = nt * 64;
        uint32_t KB = base + ((nt & 1) ? K1_U : K0_U)*4;
        __syncthreads();
        tile_cp64(base + V_U*4, vg + (size_t)n0*DD, tid);
        if (nt + 1 < ntiles) {
            uint32_t KN = base + ((nt & 1) ? K0_U : K1_U)*4;
            tile_cp64(KN, kg + (size_t)(n0 + 64)*DD, tid);
        }
        CP_COMMIT();
        CP_WAIT(1);                        // K[nt] resident
        __syncthreads();

        float sacc[4][4];
        #pragma unroll
        for (int nf = 0; nf < 4; nf++)
            #pragma unroll
            for (int i = 0; i < 4; i++) sacc[nf][i] = 0.f;
        #pragma unroll 4
        for (int s = 0; s < 16; s++) {
            uint32_t a[4];
            int arow = wm*16 + l7 + lh*8;
            ldm_x4(a, base + (uint32_t)(QS_U + arow*TSU + s*8 + lq*4)*4);
            #pragma unroll
            for (int np = 0; np < 2; np++) {
                uint32_t bfr[4];
                int brow = wn*32 + np*16 + lq*8 + l7;
                ldm_x4(bfr, KB + (uint32_t)(brow*TSU + s*8 + lh*4)*4);
                mma_bf16(sacc[np*2],   a, bfr[0], bfr[1]);
                mma_bf16(sacc[np*2+1], a, bfr[2], bfr[3]);
            }
        }
        #pragma unroll
        for (int nf = 0; nf < 4; nf++) {
            int c = wn*32 + nf*8 + 2*t;
            *(float2*)&Ssf[r0*68 + c]     = make_float2(sacc[nf][0], sacc[nf][1]);
            *(float2*)&Ssf[(r0+8)*68 + c] = make_float2(sacc[nf][2], sacc[nf][3]);
        }
        __syncthreads();

        {
            int row = tid >> 2, sub = tid & 3;
            int nv = vlen - n0; if (nv > 64) nv = 64;
            float sv[16];
            #pragma unroll
            for (int j = 0; j < 16; j++) {
                int col = sub*16 + j;
                sv[j] = (col < nv) ? Ssf[row*68 + col] : -INFINITY;
            }
            float mx = sv[0];
            #pragma unroll
            for (int j = 1; j < 16; j++) mx = fmaxf(mx, sv[j]);
            mx = fmaxf(mx, __shfl_xor_sync(0xFFFFFFFFu, mx, 1));
            mx = fmaxf(mx, __shfl_xor_sync(0xFFFFFFFFu, mx, 2));
            float mold = mrow[row];
            mx = fmaxf(mx, mold);
            float psum = 0.f;
            uint32_t pp[8];
            #pragma unroll
            for (int j = 0; j < 8; j++) {
                float p0 = __expf(sv[2*j]   - mx);
                float p1 = __expf(sv[2*j+1] - mx);
                if (sub*16 + 2*j   >= nv) p0 = 0.f;
                if (sub*16 + 2*j+1 >= nv) p1 = 0.f;
                psum += p0 + p1;
                __nv_bfloat162 pk = __floats2bfloat162_rn(p0, p1);
                pp[j] = *(uint32_t*)&pk;
            }
            psum += __shfl_xor_sync(0xFFFFFFFFu, psum, 1);
            psum += __shfl_xor_sync(0xFFFFFFFFu, psum, 2);
            uint32_t* Pu = smu + SS_U + row*68 + sub*8;
            #pragma unroll
            for (int j = 0; j < 8; j++) Pu[j] = pp[j];
            if (sub == 0) {
                float c = __expf(mold - mx);
                mrow[row] = mx;
                lrow[row] = lrow[row]*c + psum;
                crow[row] = c;
            }
        }
        CP_WAIT(0);                        // V[nt] resident
        __syncthreads();

        float c0 = crow[r0], c1 = crow[r0+8];
        #pragma unroll
        for (int nf = 0; nf < 16; nf++) {
            accO[nf][0] *= c0; accO[nf][1] *= c0;
            accO[nf][2] *= c1; accO[nf][3] *= c1;
        }
        #pragma unroll
        for (int ks = 0; ks < 4; ks++) {
            uint32_t a[4];
            int arow = wm*16 + l7 + lh*8;
            ldm_x4(a, base + (uint32_t)(SS_U + arow*68 + ks*8 + lq*4)*4);
            #pragma unroll
            for (int np = 0; np < 8; np++) {
                uint32_t bfr[4];
                int krow = ks*16 + lh*8 + l7;
                int du = wn*64 + np*8 + lq*4;
                ldm_x4_t(bfr, base + (uint32_t)(V_U + krow*TSU + du)*4);
                mma_bf16(accO[np*2],   a, bfr[0], bfr[1]);
                mma_bf16(accO[np*2+1], a, bfr[2], bfr[3]);
            }
        }
    }

    // epilogue: /l, shuffle column-max, cross-warp via smem stage
    float inv0 = 1.f / lrow[r0], inv1 = 1.f / lrow[r0+8];
    float* stage = (float*)(smu + K0_U);
    #pragma unroll
    for (int nf = 0; nf < 16; nf++) {
        float cm0 = fmaxf(accO[nf][0]*inv0, accO[nf][2]*inv1);
        float cm1 = fmaxf(accO[nf][1]*inv0, accO[nf][3]*inv1);
        #pragma unroll
        for (int o = 4; o < 32; o <<= 1) {
            cm0 = fmaxf(cm0, __shfl_xor_sync(0xFFFFFFFFu, cm0, o));
            cm1 = fmaxf(cm1, __shfl_xor_sync(0xFFFFFFFFu, cm1, o));
        }
        if (g == 0) {
            int col = wn*128 + nf*8 + 2*t;
            stage[wm*256 + col]     = cm0;
            stage[wm*256 + col + 1] = cm1;
        }
    }
    __syncthreads();
    if (tid < 256) {
        int col = tid;
        float m = stage[col];
        #pragma unroll
        for (int w = 1; w < 8; w++) m = fmaxf(m, stage[w*256 + col]);
        g_pmax[(size_t)(b*4 + ttile)*DD + col] = m;
    }
}

// ---------------------------------------------------------------------------
// K4: out[b] = sigmoid( (max_tiles(pmax) + le) . w_out + b_out )
// ---------------------------------------------------------------------------
__global__ void k_final(const int* __restrict__ labels, const float* __restrict__ emb,
                        const float* __restrict__ w_out, const float* __restrict__ b_out,
                        float* __restrict__ out) {
    int b = blockIdx.x, d = threadIdx.x;
    float m = g_pmax[(b*4 + 0)*DD + d];
    #pragma unroll
    for (int j = 1; j < 4; j++) m = fmaxf(m, g_pmax[(b*4 + j)*DD + d]);
    float val = (m + emb[labels[b]*DD + d]) * w_out[d];
    #pragma unroll
    for (int o = 16; o; o >>= 1) val += __shfl_down_sync(0xFFFFFFFFu, val, o);
    __shared__ float ws[8];
    if ((d & 31) == 0) ws[d >> 5] = val;
    __syncthreads();
    if (d == 0) {
        float s = 0.f;
        #pragma unroll
        for (int i = 0; i < 8; i++) s += ws[i];
        s += b_out[0];
        out[b] = 1.f / (1.f + expf(-s));
    }
}

// ---------------------------------------------------------------------------
extern "C" void kernel_launch(void* const* d_in, const int* in_sizes, int n_in,
                              void* d_out, int out_size) {
    const float* traj      = (const float*)d_in[0];
    const int*   labels    = (const int*)  d_in[1];
    const float* h         = (const float*)d_in[2];
    const int*   valid_len = (const int*)  d_in[3];
    const float* emb       = (const float*)d_in[4];
    const float* w_mlp     = (const float*)d_in[5];
    const float* b_mlp     = (const float*)d_in[6];
    const float* ln_g      = (const float*)d_in[7];
    const float* ln_b      = (const float*)d_in[8];
    const float* wq        = (const float*)d_in[9];
    const float* bq        = (const float*)d_in[10];
    const float* wk        = (const float*)d_in[11];
    const float* bk        = (const float*)d_in[12];
    const float* wv        = (const float*)d_in[13];
    const float* bv        = (const float*)d_in[14];
    const float* w_out     = (const float*)d_in[15];
    const float* b_out     = (const float*)d_in[16];
    float* out = (float*)d_out;

    cudaFuncSetAttribute(k_attn_tc, cudaFuncAttributeMaxDynamicSharedMemorySize, ATTN_SMEM);
    cudaFuncSetAttribute(k_qkv_tc,  cudaFuncAttributeMaxDynamicSharedMemorySize, QKV_SMEM);

    k_pre<<<PRE_END, 256>>>(h, traj, labels, emb, w_mlp, b_mlp, ln_g, ln_b, wq, wk, wv);
    k_qkv_tc<<<dim3(256, 4), 256, QKV_SMEM>>>(bk, bv, valid_len);
    k_attn_tc<<<dim3(4, BB), 512, ATTN_SMEM>>>(valid_len, bq);
    k_final<<<BB, DD>>>(labels, emb, w_out, b_out, out);
}

// round 11
// speedup vs baseline: 1.1011x; 1.1011x over previous
#include <cuda_runtime.h>
#include <cuda_bf16.h>
#include <math.h>
#include <stdint.h>

#define BB 64
#define TT 512
#define NKEY 512
#define DD 256

// Scratch (device globals: allocation-free per harness rules)
__device__ __nv_bfloat16 g_xb[BB*TT*DD];
__device__ __nv_bfloat16 g_hb[BB*NKEY*DD];
__device__ __nv_bfloat16 g_qb[BB*TT*DD];
__device__ __nv_bfloat16 g_kb[BB*NKEY*DD];
__device__ __nv_bfloat16 g_vb[BB*NKEY*DD];
__device__ __nv_bfloat16 g_wTb[3*DD*DD];   // transposed weights [z][n][k], bf16
__device__ float g_pmax[BB*8*DD];

// ---------------------------------------------------------------------------
// helpers (base PTX ISA, valid on sm_100 target)
// ---------------------------------------------------------------------------
__device__ __forceinline__ uint32_t smem_u32(const void* p) {
    uint32_t a;
    asm("{ .reg .u64 t; cvta.to.shared.u64 t, %1; cvt.u32.u64 %0, t; }" : "=r"(a) : "l"(p));
    return a;
}
__device__ __forceinline__ void mma_bf16(float* d, const uint32_t* a, uint32_t b0, uint32_t b1) {
    asm volatile(
        "mma.sync.aligned.m16n8k16.row.col.f32.bf16.bf16.f32 "
        "{%0,%1,%2,%3}, {%4,%5,%6,%7}, {%8,%9}, {%0,%1,%2,%3};"
        : "+f"(d[0]), "+f"(d[1]), "+f"(d[2]), "+f"(d[3])
        : "r"(a[0]), "r"(a[1]), "r"(a[2]), "r"(a[3]), "r"(b0), "r"(b1));
}
__device__ __forceinline__ void ldm_x4(uint32_t* r, uint32_t addr) {
    asm volatile("ldmatrix.sync.aligned.m8n8.x4.shared.b16 {%0,%1,%2,%3}, [%4];"
        : "=r"(r[0]), "=r"(r[1]), "=r"(r[2]), "=r"(r[3]) : "r"(addr));
}
__device__ __forceinline__ void ldm_x4_t(uint32_t* r, uint32_t addr) {
    asm volatile("ldmatrix.sync.aligned.m8n8.x4.trans.shared.b16 {%0,%1,%2,%3}, [%4];"
        : "=r"(r[0]), "=r"(r[1]), "=r"(r[2]), "=r"(r[3]) : "r"(addr));
}
__device__ __forceinline__ void cp_async16(uint32_t dst, const void* src) {
    asm volatile("cp.async.cg.shared.global [%0], [%1], 16;" :: "r"(dst), "l"(src));
}
#define CP_COMMIT() asm volatile("cp.async.commit_group;" ::: "memory")
#define CP_WAIT(n)  asm volatile("cp.async.wait_group %0;" :: "n"(n) : "memory")

// ---------------------------------------------------------------------------
// K_pre: fused (a) h->bf16 convert, (b) build x, (c) weight transpose.
// ---------------------------------------------------------------------------
#define PRE_PREP 8192
#define PRE_BX   (PRE_PREP + 4096)
#define PRE_END  (PRE_BX + 24)

__global__ __launch_bounds__(256) void k_pre(const float* __restrict__ h,
        const float* __restrict__ traj, const int* __restrict__ labels,
        const float* __restrict__ emb, const float* __restrict__ w_mlp,
        const float* __restrict__ b_mlp, const float* __restrict__ ln_g,
        const float* __restrict__ ln_b, const float* __restrict__ wq,
        const float* __restrict__ wk, const float* __restrict__ wv) {
    __shared__ float s[32*257];
    int bx = blockIdx.x;
    int tid = threadIdx.x;

    if (bx < PRE_PREP) {
        size_t i = (size_t)bx * 256 + tid;
        float4 v = *(const float4*)&h[i*4];
        __nv_bfloat162 p0 = __floats2bfloat162_rn(v.x, v.y);
        __nv_bfloat162 p1 = __floats2bfloat162_rn(v.z, v.w);
        uint32_t* dst = (uint32_t*)&g_hb[i*4];
        dst[0] = *(uint32_t*)&p0;
        dst[1] = *(uint32_t*)&p1;
    } else if (bx < PRE_BX) {
        int warp = tid >> 5, lane = tid & 31;
        int row = (bx - PRE_PREP)*8 + warp;
        int b = row >> 9;
        float t0 = traj[row*2 + 0];
        float t1 = traj[row*2 + 1];
        int lab = labels[b];
        float v[8];
        float sm = 0.f, s2 = 0.f;
        #pragma unroll
        for (int j = 0; j < 8; j++) {
            int d = lane + 32*j;
            v[j] = t0*w_mlp[d] + t1*w_mlp[DD + d] + b_mlp[d];
            sm += v[j]; s2 += v[j]*v[j];
        }
        #pragma unroll
        for (int o = 16; o; o >>= 1) {
            sm += __shfl_xor_sync(0xFFFFFFFFu, sm, o);
            s2 += __shfl_xor_sync(0xFFFFFFFFu, s2, o);
        }
        float mu  = sm * (1.f/DD);
        float var = s2 * (1.f/DD) - mu*mu;
        float rs  = rsqrtf(var + 1e-5f);
        __nv_bfloat16* dst = g_xb + (size_t)row*DD;
        #pragma unroll
        for (int j = 0; j < 8; j++) {
            int d = lane + 32*j;
            float y = (v[j] - mu) * rs * ln_g[d] + ln_b[d];
            y = (y >= 0.f) ? y : 0.01f * y;
            y += emb[lab*DD + d];
            dst[d] = __float2bfloat16(y);
        }
    } else {
        int idx = bx - PRE_BX;
        int z = idx >> 3;
        int k0 = (idx & 7) * 32;
        const float* W = (z == 0) ? wq : (z == 1) ? wk : wv;
        #pragma unroll
        for (int i = 0; i < 32; i++) {
            int f = tid + i*256;
            int k = f >> 8, n = f & 255;
            s[k*257 + n] = W[(k0 + k)*DD + n];
        }
        __syncthreads();
        int n = tid;
        __nv_bfloat16* dst = &g_wTb[(size_t)z*DD*DD + (size_t)n*DD + k0];
        #pragma unroll
        for (int j = 0; j < 32; j++)
            dst[j] = __float2bfloat16(s[j*257 + n]);
    }
}

// ---------------------------------------------------------------------------
// K2: bf16 mma GEMM (R8-proven): q/k/v, cp.async double-buffered K-chunks.
// blockIdx.y: 0,1 -> q n-tiles; 2,3 -> k; 4,5 -> v.
// k/v m-tiles fully beyond valid_len[b] are dead -> early-exit.
// ---------------------------------------------------------------------------
#define GS 36
#define QKV_BUF (2*128*GS)
#define QKV_SMEM (2*QKV_BUF*4)

__global__ __launch_bounds__(256) void k_qkv_tc(const float* __restrict__ bq,
        const float* __restrict__ bk, const float* __restrict__ bv,
        const int* __restrict__ valid_len) {
    int y = blockIdx.y;
    int z = y >> 1;
    if (z >= 1) {
        int bb = blockIdx.x >> 2;
        int tib = blockIdx.x & 3;
        if (tib * 128 >= valid_len[bb]) return;
    }

    extern __shared__ uint32_t qsm[];
    uint32_t base = smem_u32(qsm);

    int tid = threadIdx.x;
    int wid = tid >> 5, lane = tid & 31;
    int g = lane >> 2, t = lane & 3;
    int wm = wid & 3, wn = wid >> 2;
    int l7 = lane & 7, lh = (lane >> 3) & 1, lq = lane >> 4;
    int m0 = blockIdx.x * 128;
    int n0 = (y & 1) * 128;

    const __nv_bfloat16* A  = (z == 0) ? g_xb : g_hb;
    const __nv_bfloat16* WT = g_wTb + (size_t)z*DD*DD;
    const float* bias = (z == 0) ? bq : (z == 1) ? bk : bv;
    __nv_bfloat16* Out = (z == 0) ? g_qb : (z == 1) ? g_kb : g_vb;
    float oscale = (z == 0) ? 0.0625f : 1.f;

    auto fill = [&](int buf, int kc) {
        uint32_t ab = base + (uint32_t)buf*QKV_BUF*4;
        uint32_t bb = ab + 128*GS*4;
        int k0 = kc * 64;
        #pragma unroll
        for (int i = 0; i < 4; i++) {
            int f = tid + i*256;
            int r = f >> 3, cu = (f & 7) * 4;
            cp_async16(ab + (uint32_t)(r*GS + cu)*4, A  + (size_t)(m0 + r)*DD + k0 + cu*2);
            cp_async16(bb + (uint32_t)(r*GS + cu)*4, WT + (size_t)(n0 + r)*DD + k0 + cu*2);
        }
    };

    float acc[2][8][4];
    #pragma unroll
    for (int mf = 0; mf < 2; mf++)
        #pragma unroll
        for (int nf = 0; nf < 8; nf++)
            #pragma unroll
            for (int i = 0; i < 4; i++) acc[mf][nf][i] = 0.f;

    fill(0, 0);
    CP_COMMIT();

    for (int kc = 0; kc < 4; kc++) {
        int buf = kc & 1;
        if (kc < 3) { fill(buf ^ 1, kc + 1); CP_COMMIT(); CP_WAIT(1); }
        else        { CP_WAIT(0); }
        __syncthreads();

        uint32_t asb = base + (uint32_t)buf*QKV_BUF*4;
        uint32_t bsb = asb + 128*GS*4;
        #pragma unroll
        for (int s = 0; s < 4; s++) {
            uint32_t a[2][4];
            #pragma unroll
            for (int mf = 0; mf < 2; mf++) {
                int row = wm*32 + mf*16 + l7 + lh*8;
                ldm_x4(a[mf], asb + (uint32_t)(row*GS + s*8 + lq*4)*4);
            }
            #pragma unroll
            for (int np = 0; np < 4; np++) {
                uint32_t b[4];
                int row = wn*64 + np*16 + lq*8 + l7;
                ldm_x4(b, bsb + (uint32_t)(row*GS + s*8 + lh*4)*4);
                mma_bf16(acc[0][np*2],   a[0], b[0], b[1]);
                mma_bf16(acc[1][np*2],   a[1], b[0], b[1]);
                mma_bf16(acc[0][np*2+1], a[0], b[2], b[3]);
                mma_bf16(acc[1][np*2+1], a[1], b[2], b[3]);
            }
        }
        __syncthreads();
    }

    #pragma unroll
    for (int mf = 0; mf < 2; mf++) {
        int r = m0 + wm*32 + mf*16 + g;
        #pragma unroll
        for (int nf = 0; nf < 8; nf++) {
            int col = n0 + wn*64 + nf*8 + 2*t;
            float b0 = bias[col], b1 = bias[col+1];
            __nv_bfloat162 v0 = __floats2bfloat162_rn((acc[mf][nf][0]+b0)*oscale,
                                                      (acc[mf][nf][1]+b1)*oscale);
            __nv_bfloat162 v1 = __floats2bfloat162_rn((acc[mf][nf][2]+b0)*oscale,
                                                      (acc[mf][nf][3]+b1)*oscale);
            *(uint32_t*)&Out[(size_t)r*DD + col]     = *(uint32_t*)&v0;
            *(uint32_t*)&Out[(size_t)(r+8)*DD + col] = *(uint32_t*)&v1;
        }
    }
}

// ---------------------------------------------------------------------------
// K3: bf16 mma flash attention, 64-row t-tiles, 256 threads, 102KB smem
// -> 2 CTAs/SM. Single K buffer (S/P overlaid on it after S-mma), single
// V buffer prefetched during softmax. Grid (8 t-tiles, 64 b).
// Warps: wm = wid>>1 (16 rows), wn = wid&1 (32 S-cols / 128 d-cols).
// ---------------------------------------------------------------------------
#define TSU 132
#define QS_U 0
#define KS_U 8448              // K tile; S/P overlaid here (stride 68) after S-mma
#define VS_U 16896
#define MR_U 25344
#define LR_U 25408
#define CR_U 25472
#define ATTN_SMEM (25536*4)    // 102144 B -> 2 CTAs/SM

// copy one 64x256 bf16 tile into smem at stride TSU (256 threads)
__device__ __forceinline__ void tile_cp64(uint32_t dst_base, const __nv_bfloat16* src, int tid) {
    #pragma unroll
    for (int i = 0; i < 8; i++) {
        int c = tid + i*256;
        int r = c >> 5, o = c & 31;
        cp_async16(dst_base + (uint32_t)(r*TSU + o*4)*4, src + (size_t)r*DD + o*8);
    }
}

__global__ __launch_bounds__(256, 2) void k_attn_tc(const int* __restrict__ valid_len) {
    extern __shared__ uint32_t smu[];
    uint32_t base = smem_u32(smu);
    float* Ssf  = (float*)(smu + KS_U);       // S/P overlay, stride 68 u32
    float* mrow = (float*)(smu + MR_U);
    float* lrow = (float*)(smu + LR_U);
    float* crow = (float*)(smu + CR_U);

    int tid = threadIdx.x;
    int wid = tid >> 5, lane = tid & 31;
    int g = lane >> 2, t = lane & 3;
    int l7 = lane & 7, lh = (lane >> 3) & 1, lq = lane >> 4;
    int wm = wid >> 1, wn = wid & 1;
    int b = blockIdx.y, ttile = blockIdx.x;
    int vlen = valid_len[b];
    int ntiles = (vlen + 63) >> 6;
    int r0 = wm*16 + g;

    const __nv_bfloat16* qg = g_qb + (size_t)(b*TT + ttile*64)*DD;
    const __nv_bfloat16* kg = g_kb + (size_t)b*NKEY*DD;
    const __nv_bfloat16* vg = g_vb + (size_t)b*NKEY*DD;

    // prologue: one group = {Q, K0, V0}
    tile_cp64(base + QS_U*4, qg, tid);
    tile_cp64(base + KS_U*4, kg, tid);
    tile_cp64(base + VS_U*4, vg, tid);
    CP_COMMIT();
    if (tid < 64) { mrow[tid] = -INFINITY; lrow[tid] = 0.f; }

    float accO[16][4];
    #pragma unroll
    for (int nf = 0; nf < 16; nf++)
        #pragma unroll
        for (int i = 0; i < 4; i++) accO[nf][i] = 0.f;

    for (int nt = 0; nt < ntiles; nt++) {
        int n0 = nt * 64;
        CP_WAIT(0);                        // K[nt] (iter0: also Q, V0) resident
        __syncthreads();

        // S = Q.K^T : warp tile 16 rows x 32 cols, 16 k16 steps
        float sacc[4][4];
        #pragma unroll
        for (int nf = 0; nf < 4; nf++)
            #pragma unroll
            for (int i = 0; i < 4; i++) sacc[nf][i] = 0.f;
        #pragma unroll 4
        for (int s = 0; s < 16; s++) {
            uint32_t a[4];
            int arow = wm*16 + l7 + lh*8;
            ldm_x4(a, base + (uint32_t)(QS_U + arow*TSU + s*8 + lq*4)*4);
            #pragma unroll
            for (int np = 0; np < 2; np++) {
                uint32_t bfr[4];
                int brow = wn*32 + np*16 + lq*8 + l7;
                ldm_x4(bfr, base + (uint32_t)(KS_U + brow*TSU + s*8 + lh*4)*4);
                mma_bf16(sacc[np*2],   a, bfr[0], bfr[1]);
                mma_bf16(sacc[np*2+1], a, bfr[2], bfr[3]);
            }
        }
        __syncthreads();                   // ALL warps done reading K

        // prefetch V[nt] (nt>=1; V0 came with prologue group)
        if (nt >= 1) {
            tile_cp64(base + VS_U*4, vg + (size_t)n0*DD, tid);
            CP_COMMIT();
        }
        // store S into the (now free) K region, stride 68
        #pragma unroll
        for (int nf = 0; nf < 4; nf++) {
            int c = wn*32 + nf*8 + 2*t;
            *(float2*)&Ssf[r0*68 + c]     = make_float2(sacc[nf][0], sacc[nf][1]);
            *(float2*)&Ssf[(r0+8)*68 + c] = make_float2(sacc[nf][2], sacc[nf][3]);
        }
        __syncthreads();                   // S visible

        // softmax: 4 threads/row, 16 cols each; P (bf16) overwrites S
        {
            int row = tid >> 2, sub = tid & 3;
            int nv = vlen - n0; if (nv > 64) nv = 64;
            float sv[16];
            #pragma unroll
            for (int j = 0; j < 16; j++) {
                int col = sub*16 + j;
                sv[j] = (col < nv) ? Ssf[row*68 + col] : -INFINITY;
            }
            float mx = sv[0];
            #pragma unroll
            for (int j = 1; j < 16; j++) mx = fmaxf(mx, sv[j]);
            mx = fmaxf(mx, __shfl_xor_sync(0xFFFFFFFFu, mx, 1));
            mx = fmaxf(mx, __shfl_xor_sync(0xFFFFFFFFu, mx, 2));
            float mold = mrow[row];
            mx = fmaxf(mx, mold);
            float psum = 0.f;
            uint32_t pp[8];
            #pragma unroll
            for (int j = 0; j < 8; j++) {
                float p0 = __expf(sv[2*j]   - mx);
                float p1 = __expf(sv[2*j+1] - mx);
                if (sub*16 + 2*j   >= nv) p0 = 0.f;
                if (sub*16 + 2*j+1 >= nv) p1 = 0.f;
                psum += p0 + p1;
                __nv_bfloat162 pk = __floats2bfloat162_rn(p0, p1);
                pp[j] = *(uint32_t*)&pk;
            }
            psum += __shfl_xor_sync(0xFFFFFFFFu, psum, 1);
            psum += __shfl_xor_sync(0xFFFFFFFFu, psum, 2);
            uint32_t* Pu = smu + KS_U + row*68 + sub*8;
            #pragma unroll
            for (int j = 0; j < 8; j++) Pu[j] = pp[j];
            if (sub == 0) {
                float c = __expf(mold - mx);
                mrow[row] = mx;
                lrow[row] = lrow[row]*c + psum;
                crow[row] = c;
            }
        }
        CP_WAIT(0);                        // V[nt] resident
        __syncthreads();                   // P + V visible

        // O rescale + O += P.V : warp tile 16 rows x 128 d-cols, 4 k16 steps
        float c0 = crow[r0], c1 = crow[r0+8];
        #pragma unroll
        for (int nf = 0; nf < 16; nf++) {
            accO[nf][0] *= c0; accO[nf][1] *= c0;
            accO[nf][2] *= c1; accO[nf][3] *= c1;
        }
        #pragma unroll
        for (int ks = 0; ks < 4; ks++) {
            uint32_t a[4];
            int arow = wm*16 + l7 + lh*8;
            ldm_x4(a, base + (uint32_t)(KS_U + arow*68 + ks*8 + lq*4)*4);
            #pragma unroll
            for (int np = 0; np < 8; np++) {
                uint32_t bfr[4];
                int krow = ks*16 + lh*8 + l7;
                int du = wn*64 + np*8 + lq*4;
                ldm_x4_t(bfr, base + (uint32_t)(VS_U + krow*TSU + du)*4);
                mma_bf16(accO[np*2],   a, bfr[0], bfr[1]);
                mma_bf16(accO[np*2+1], a, bfr[2], bfr[3]);
            }
        }
        __syncthreads();                   // PV done reading P (K region) & V
        if (nt + 1 < ntiles) {
            tile_cp64(base + KS_U*4, kg + (size_t)(n0 + 64)*DD, tid);
            CP_COMMIT();
        }
    }

    // epilogue: /l, shuffle column-max over 16 rows, cross-warp via K-region stage
    float inv0 = 1.f / lrow[r0], inv1 = 1.f / lrow[r0+8];
    float* stage = (float*)(smu + KS_U);   // [4 wm][256 cols]; safe: loop's last
                                           // sync guarantees PV reads done, and
                                           // no K prefetch was issued (nt==last)
    #pragma unroll
    for (int nf = 0; nf < 16; nf++) {
        float cm0 = fmaxf(accO[nf][0]*inv0, accO[nf][2]*inv1);
        float cm1 = fmaxf(accO[nf][1]*inv0, accO[nf][3]*inv1);
        #pragma unroll
        for (int o = 4; o < 32; o <<= 1) {
            cm0 = fmaxf(cm0, __shfl_xor_sync(0xFFFFFFFFu, cm0, o));
            cm1 = fmaxf(cm1, __shfl_xor_sync(0xFFFFFFFFu, cm1, o));
        }
        if (g == 0) {
            int col = wn*128 + nf*8 + 2*t;
            stage[wm*256 + col]     = cm0;
            stage[wm*256 + col + 1] = cm1;
        }
    }
    __syncthreads();
    {
        int col = tid;
        float m = stage[col];
        #pragma unroll
        for (int w = 1; w < 4; w++) m = fmaxf(m, stage[w*256 + col]);
        g_pmax[(size_t)(b*8 + ttile)*DD + col] = m;
    }
}

// ---------------------------------------------------------------------------
// K4: out[b] = sigmoid( (max_tiles(pmax) + le) . w_out + b_out )
// ---------------------------------------------------------------------------
__global__ void k_final(const int* __restrict__ labels, const float* __restrict__ emb,
                        const float* __restrict__ w_out, const float* __restrict__ b_out,
                        float* __restrict__ out) {
    int b = blockIdx.x, d = threadIdx.x;
    float m = g_pmax[(b*8 + 0)*DD + d];
    #pragma unroll
    for (int j = 1; j < 8; j++) m = fmaxf(m, g_pmax[(b*8 + j)*DD + d]);
    float val = (m + emb[labels[b]*DD + d]) * w_out[d];
    #pragma unroll
    for (int o = 16; o; o >>= 1) val += __shfl_down_sync(0xFFFFFFFFu, val, o);
    __shared__ float ws[8];
    if ((d & 31) == 0) ws[d >> 5] = val;
    __syncthreads();
    if (d == 0) {
        float s = 0.f;
        #pragma unroll
        for (int i = 0; i < 8; i++) s += ws[i];
        s += b_out[0];
        out[b] = 1.f / (1.f + expf(-s));
    }
}

// ---------------------------------------------------------------------------
extern "C" void kernel_launch(void* const* d_in, const int* in_sizes, int n_in,
                              void* d_out, int out_size) {
    const float* traj      = (const float*)d_in[0];
    const int*   labels    = (const int*)  d_in[1];
    const float* h         = (const float*)d_in[2];
    const int*   valid_len = (const int*)  d_in[3];
    const float* emb       = (const float*)d_in[4];
    const float* w_mlp     = (const float*)d_in[5];
    const float* b_mlp     = (const float*)d_in[6];
    const float* ln_g      = (const float*)d_in[7];
    const float* ln_b      = (const float*)d_in[8];
    const float* wq        = (const float*)d_in[9];
    const float* bq        = (const float*)d_in[10];
    const float* wk        = (const float*)d_in[11];
    const float* bk        = (const float*)d_in[12];
    const float* wv        = (const float*)d_in[13];
    const float* bv        = (const float*)d_in[14];
    const float* w_out     = (const float*)d_in[15];
    const float* b_out     = (const float*)d_in[16];
    float* out = (float*)d_out;

    cudaFuncSetAttribute(k_attn_tc, cudaFuncAttributeMaxDynamicSharedMemorySize, ATTN_SMEM);
    cudaFuncSetAttribute(k_qkv_tc,  cudaFuncAttributeMaxDynamicSharedMemorySize, QKV_SMEM);

    k_pre<<<PRE_END, 256>>>(h, traj, labels, emb, w_mlp, b_mlp, ln_g, ln_b, wq, wk, wv);
    k_qkv_tc<<<dim3(256, 6), 256, QKV_SMEM>>>(bq, bk, bv, valid_len);
    k_attn_tc<<<dim3(8, BB), 256, ATTN_SMEM>>>(valid_len);
    k_final<<<BB, DD>>>(labels, emb, w_out, b_out, out);
}